// round 3
// baseline (speedup 1.0000x reference)
#include <cuda_runtime.h>
#include <math.h>

#define BB 16      // batch
#define TT 1024    // sequence
#define JJ 128     // input dim
#define HH 64      // hidden (complex) dim

// Scratch: Bx in [b][t][h] layout (natural for both GEMM epilogue and scan).
__device__ float g_Bxt[BB * TT * HH];   // 4 MB static scratch

typedef unsigned long long ull;

__device__ __forceinline__ void fma2(ull& acc, ull a, ull b) {
    asm("fma.rn.f32x2 %0, %1, %2, %0;" : "+l"(acc) : "l"(a), "l"(b));
}
__device__ __forceinline__ ull add2(ull a, ull b) {
    ull r;
    asm("add.rn.f32x2 %0, %1, %2;" : "=l"(r) : "l"(a), "l"(b));
    return r;
}
__device__ __forceinline__ void unpack2(ull p, float& lo, float& hi) {
    asm("mov.b64 {%0, %1}, %2;" : "=f"(lo), "=f"(hi) : "l"(p));
}

// ---------------------------------------------------------------------------
// Kernel 1: Bxt[b][t][h] = sum_j B[h][j] * x[b][t][j]
// 128 blocks (1/SM) x 512 threads = 4 k-groups of 128.
// Each k-group: same 128t x 64h tile, its own 32-j chunk (in-block split-K),
// thread tile 8t x 8h, f32x2 FMAs fed mov-free from LDS.128.
// Fixed-order smem reduction of the 4 partials, then [t][h] epilogue.
// ---------------------------------------------------------------------------
#define XST 132
#define BST 164
#define GEMM_SMEM_BYTES ((128 * XST + 128 * BST) * 4)   // ~151.5 KB

__global__ __launch_bounds__(512) void gemm_kernel(const float* __restrict__ x,
                                                   const float* __restrict__ Bm) {
    extern __shared__ __align__(16) float smem[];
    float* xs  = smem;               // [j 0..127][t 0..127] stride XST
    float* bsd = smem + 128 * XST;   // [j 0..127][h dup]    stride BST

    const int tid = threadIdx.x;
    const int kg  = tid >> 7;        // 0..3: j-chunk owner
    const int l   = tid & 127;
    const int tx  = l & 15;          // 8 t each
    const int ty  = l >> 4;          // 8 h each
    const int b   = blockIdx.x >> 3;
    const int t0  = (blockIdx.x & 7) * 128;

    const float4* x4 = reinterpret_cast<const float4*>(x);
    const float4* B4 = reinterpret_cast<const float4*>(Bm);

    // Cooperative staging of the FULL j range (each warp reads whole rows).
#pragma unroll
    for (int i = 0; i < 8; ++i) {              // x: 128t x 32 float4
        int f  = tid + 512 * i;
        int t  = f >> 5;
        int jq = f & 31;
        float4 v = x4[(b * TT + t0 + t) * 32 + jq];
        int base = (4 * jq) * XST + t;
        xs[base]           = v.x;
        xs[base + XST]     = v.y;
        xs[base + 2 * XST] = v.z;
        xs[base + 3 * XST] = v.w;
    }
#pragma unroll
    for (int i = 0; i < 4; ++i) {              // B: 64h x 32 float4, duplicated
        int f  = tid + 512 * i;
        int h  = f >> 5;
        int jq = f & 31;
        float4 v = B4[h * 32 + jq];
        int go = (h >> 3) * 20 + (h & 7) * 2;
        int rb = (4 * jq) * BST + go;
        *reinterpret_cast<float2*>(&bsd[rb])           = make_float2(v.x, v.x);
        *reinterpret_cast<float2*>(&bsd[rb + BST])     = make_float2(v.y, v.y);
        *reinterpret_cast<float2*>(&bsd[rb + 2 * BST]) = make_float2(v.z, v.z);
        *reinterpret_cast<float2*>(&bsd[rb + 3 * BST]) = make_float2(v.w, v.w);
    }
    __syncthreads();

    ull acc[8][4];
#pragma unroll
    for (int a = 0; a < 8; ++a)
#pragma unroll
        for (int p = 0; p < 4; ++p) acc[a][p] = 0ull;

#pragma unroll 8
    for (int jj = 0; jj < 32; ++jj) {
        const int jrow = kg * 32 + jj;
        const ulonglong2* xr =
            reinterpret_cast<const ulonglong2*>(&xs[jrow * XST + tx * 8]);
        ulonglong2 xa = xr[0];
        ulonglong2 xb = xr[1];
        const ulonglong2* br =
            reinterpret_cast<const ulonglong2*>(&bsd[jrow * BST + ty * 20]);
        ulonglong2 b01 = br[0];
        ulonglong2 b23 = br[1];
        const ulonglong2* br2 =
            reinterpret_cast<const ulonglong2*>(&bsd[jrow * BST + ty * 20 + 8]);
        ulonglong2 b45 = br2[0];
        ulonglong2 b67 = br2[1];

        ull xp[4] = {xa.x, xa.y, xb.x, xb.y};
        ull bd[8] = {b01.x, b01.y, b23.x, b23.y, b45.x, b45.y, b67.x, b67.y};
#pragma unroll
        for (int a = 0; a < 8; ++a)
#pragma unroll
            for (int p = 0; p < 4; ++p) fma2(acc[a][p], bd[a], xp[p]);
    }
    __syncthreads();

    // Fixed-order split-K reduction through smem (alias staging buffers).
    ull* rbuf = reinterpret_cast<ull*>(smem);   // 256 rows x 33 ull = 67.6 KB
    if (kg == 2 || kg == 3) {
        ull* row = &rbuf[((kg - 2) * 128 + l) * 33];
#pragma unroll
        for (int a = 0; a < 8; ++a)
#pragma unroll
            for (int p = 0; p < 4; ++p) row[a * 4 + p] = acc[a][p];
    }
    __syncthreads();
    if (kg == 0 || kg == 1) {
        const ull* row = &rbuf[(kg * 128 + l) * 33];
#pragma unroll
        for (int a = 0; a < 8; ++a)
#pragma unroll
            for (int p = 0; p < 4; ++p) acc[a][p] = add2(acc[a][p], row[a * 4 + p]);
    }
    __syncthreads();
    if (kg == 1) {
        ull* row = &rbuf[l * 33];
#pragma unroll
        for (int a = 0; a < 8; ++a)
#pragma unroll
            for (int p = 0; p < 4; ++p) row[a * 4 + p] = acc[a][p];
    }
    __syncthreads();
    if (kg == 0) {
        const ull* row = &rbuf[l * 33];
        float r[8][8];    // [h-local][t-local]
#pragma unroll
        for (int a = 0; a < 8; ++a)
#pragma unroll
            for (int p = 0; p < 4; ++p) {
                ull s = add2(acc[a][p], row[a * 4 + p]);
                unpack2(s, r[a][2 * p], r[a][2 * p + 1]);
            }
        // Epilogue: Bxt[b][t][h], per t one 8h segment = 2 float4 stores.
#pragma unroll
        for (int i = 0; i < 8; ++i) {
            float* dst = &g_Bxt[(b * TT + t0 + tx * 8 + i) * HH + ty * 8];
            *reinterpret_cast<float4*>(dst) =
                make_float4(r[0][i], r[1][i], r[2][i], r[3][i]);
            *reinterpret_cast<float4*>(dst + 4) =
                make_float4(r[4][i], r[5][i], r[6][i], r[7][i]);
        }
    }
}

// ---------------------------------------------------------------------------
// Kernel 2: complex linear scan  y_t = lam*y_{t-1} + Bx_t,  y_{-1} = 1.
// Block = (b, 8 h). 128 threads = 64 t-chunks (16 steps) x 2 h-quads.
// Each thread runs 4 independent h-chains (ILP), loads/stores float4 over h.
// Carry combine: pair-fold + warp Kogge-Stone (ratio Q = lam^32).
// ---------------------------------------------------------------------------
#define CST 66   // carry array row stride

__global__ __launch_bounds__(128) void scan_kernel(const float* __restrict__ nu,
                                                   const float* __restrict__ theta,
                                                   float* __restrict__ out) {
    __shared__ float slr[8], sli[8];
    __shared__ float car_r[8 * CST], car_i[8 * CST];

    const int tid = threadIdx.x;
    const int tg  = tid >> 1;          // 0..63 t-chunk
    const int hq  = tid & 1;           // h-quad within block
    const int b   = blockIdx.y;
    const int h0  = blockIdx.x * 8;

    if (tid < 8) {
        float m = expf(-expf(nu[h0 + tid]));
        float s, c;
        sincosf(theta[h0 + tid], &s, &c);
        slr[tid] = m * c;
        sli[tid] = m * s;
    }
    __syncthreads();

    float lr[4], li[4];
#pragma unroll
    for (int c = 0; c < 4; ++c) {
        lr[c] = slr[hq * 4 + c];
        li[c] = sli[hq * 4 + c];
    }

    // Load 16 steps x 4 h (float4 over consecutive h).
    float4 u[16];
    const float* base = &g_Bxt[(b * TT + tg * 16) * HH + h0 + hq * 4];
#pragma unroll
    for (int k = 0; k < 16; ++k)
        u[k] = *reinterpret_cast<const float4*>(base + k * HH);

    // Phase A: 4 independent local scans from zero -> chunk carries.
    float yr[4] = {0.f, 0.f, 0.f, 0.f}, yi[4] = {0.f, 0.f, 0.f, 0.f};
#pragma unroll
    for (int k = 0; k < 16; ++k) {
        float uu[4] = {u[k].x, u[k].y, u[k].z, u[k].w};
#pragma unroll
        for (int c = 0; c < 4; ++c) {
            float nyr = fmaf(lr[c], yr[c], fmaf(-li[c], yi[c], uu[c]));
            float nyi = fmaf(lr[c], yi[c], li[c] * yr[c]);
            yr[c] = nyr; yi[c] = nyi;
        }
    }
#pragma unroll
    for (int c = 0; c < 4; ++c) {
        car_r[(hq * 4 + c) * CST + tg] = yr[c];
        car_i[(hq * 4 + c) * CST + tg] = yi[c];
    }
    __syncthreads();

    // Phase B: 4 warps, each handles 2 local h. 64 carries/h -> pair-fold to
    // 32, Kogge-Stone with ratio Q = P^2 (P = lam^16), then expand.
    {
        const int lane = tid & 31;
        const int wid  = tid >> 5;
#pragma unroll
        for (int sub = 0; sub < 2; ++sub) {
            const int hh = wid * 2 + sub;
            const float alr = slr[hh], ali = sli[hh];
            // P = lam^16 via 4 squarings
            float pr = alr, pi = ali;
#pragma unroll
            for (int s = 0; s < 4; ++s) {
                float nr = pr * pr - pi * pi;
                float ni = 2.f * pr * pi;
                pr = nr; pi = ni;
            }
            // Q^(2^d), d=0..4  (Q = P^2)
            float Qr[5], Qi[5];
            Qr[0] = pr * pr - pi * pi;
            Qi[0] = 2.f * pr * pi;
#pragma unroll
            for (int d = 1; d < 5; ++d) {
                Qr[d] = Qr[d - 1] * Qr[d - 1] - Qi[d - 1] * Qi[d - 1];
                Qi[d] = 2.f * Qr[d - 1] * Qi[d - 1];
            }
            float v0r = car_r[hh * CST + 2 * lane];
            float v0i = car_i[hh * CST + 2 * lane];
            float v1r = car_r[hh * CST + 2 * lane + 1];
            float v1i = car_i[hh * CST + 2 * lane + 1];
            // U = V1 + P*V0
            float Ir = v1r + (pr * v0r - pi * v0i);
            float Ii = v1i + (pr * v0i + pi * v0r);
            // KS inclusive scan, ratio Q
#pragma unroll
            for (int d = 0; d < 5; ++d) {
                int sh = 1 << d;
                float orr = __shfl_up_sync(0xffffffffu, Ir, sh);
                float oii = __shfl_up_sync(0xffffffffu, Ii, sh);
                if (lane >= sh) {
                    Ir = Ir + (Qr[d] * orr - Qi[d] * oii);
                    Ii = Ii + (Qr[d] * oii + Qi[d] * orr);
                }
            }
            // exclusive
            float Xr = __shfl_up_sync(0xffffffffu, Ir, 1);
            float Xi = __shfl_up_sync(0xffffffffu, Ii, 1);
            if (lane == 0) { Xr = 0.f; Xi = 0.f; }
            // Q^lane
            float qr = 1.f, qi = 0.f;
#pragma unroll
            for (int d = 0; d < 5; ++d) {
                if ((lane >> d) & 1) {
                    float nr = qr * Qr[d] - qi * Qi[d];
                    float ni = qr * Qi[d] + qi * Qr[d];
                    qr = nr; qi = ni;
                }
            }
            // S_{2l} = Q^l (y_{-1}=1) + X_l ;  S_{2l+1} = P*S_{2l} + V0
            float S0r = qr + Xr, S0i = qi + Xi;
            float S1r = fmaf(pr, S0r, fmaf(-pi, S0i, v0r));
            float S1i = fmaf(pr, S0i, fmaf(pi, S0r, v0i));
            car_r[hh * CST + 2 * lane]     = S0r;
            car_i[hh * CST + 2 * lane]     = S0i;
            car_r[hh * CST + 2 * lane + 1] = S1r;
            car_i[hh * CST + 2 * lane + 1] = S1i;
        }
    }
    __syncthreads();

    // Phase C: rerun with true incoming states; float4 stores (re & im).
#pragma unroll
    for (int c = 0; c < 4; ++c) {
        yr[c] = car_r[(hq * 4 + c) * CST + tg];
        yi[c] = car_i[(hq * 4 + c) * CST + tg];
    }
    float* op = out + (b * TT + tg * 16) * (2 * HH) + h0 + hq * 4;
#pragma unroll
    for (int k = 0; k < 16; ++k) {
        float uu[4] = {u[k].x, u[k].y, u[k].z, u[k].w};
#pragma unroll
        for (int c = 0; c < 4; ++c) {
            float nyr = fmaf(lr[c], yr[c], fmaf(-li[c], yi[c], uu[c]));
            float nyi = fmaf(lr[c], yi[c], li[c] * yr[c]);
            yr[c] = nyr; yi[c] = nyi;
        }
        *reinterpret_cast<float4*>(op + k * 128) =
            make_float4(yr[0], yr[1], yr[2], yr[3]);
        *reinterpret_cast<float4*>(op + k * 128 + 64) =
            make_float4(yi[0], yi[1], yi[2], yi[3]);
    }
}

// ---------------------------------------------------------------------------
extern "C" void kernel_launch(void* const* d_in, const int* in_sizes, int n_in,
                              void* d_out, int out_size) {
    const float* x     = (const float*)d_in[0];   // [16,1024,128]
    const float* Bm    = (const float*)d_in[1];   // [64,128]
    const float* nu    = (const float*)d_in[2];   // [64]
    const float* theta = (const float*)d_in[3];   // [64]
    float* out = (float*)d_out;                   // [16,1024,128]

    cudaFuncSetAttribute(gemm_kernel,
                         cudaFuncAttributeMaxDynamicSharedMemorySize,
                         GEMM_SMEM_BYTES);
    gemm_kernel<<<128, 512, GEMM_SMEM_BYTES>>>(x, Bm);
    scan_kernel<<<dim3(8, 16), 128>>>(nu, theta, out);
}

// round 4
// speedup vs baseline: 1.4785x; 1.4785x over previous
#include <cuda_runtime.h>
#include <math.h>

#define BB 16      // batch
#define TT 1024    // sequence
#define JJ 128     // input dim
#define HH 64      // hidden (complex) dim

// Scratch: Bx in [b][h][t] layout (contiguous t rows for the scan).
__device__ float g_Bxt[BB * HH * TT];   // 4 MB static scratch

// ---------------------------------------------------------------------------
// tf32 helpers
// ---------------------------------------------------------------------------
__device__ __forceinline__ unsigned tf32bits(float v) {
    unsigned r;
    asm("cvt.rna.tf32.f32 %0, %1;" : "=r"(r) : "f"(v));
    return r;
}
__device__ __forceinline__ void mma_tf32(float& d0, float& d1, float& d2, float& d3,
                                         unsigned a0, unsigned a1, unsigned a2, unsigned a3,
                                         unsigned b0, unsigned b1) {
    asm("mma.sync.aligned.m16n8k8.row.col.f32.tf32.tf32.f32 "
        "{%0,%1,%2,%3}, {%4,%5,%6,%7}, {%8,%9}, {%0,%1,%2,%3};"
        : "+f"(d0), "+f"(d1), "+f"(d2), "+f"(d3)
        : "r"(a0), "r"(a1), "r"(a2), "r"(a3), "r"(b0), "r"(b1));
}
__device__ __forceinline__ unsigned fbits(float v) { return __float_as_uint(v); }

// ---------------------------------------------------------------------------
// Kernel 1: Bxt[b][h][t] = sum_j B[h][j] * x[b][t][j]   (3xTF32 tensor-core)
// Grid 256 = 16 b x 4 t-segs... (b = bid>>4, t0 = (bid&15)*64).
// Block 128 thr = 4 warps in 2x2 (t,h); warp tile 32t x 32h = 2 m-tiles x 4
// n-tiles of m16n8k8. K=128 in 2 chunks of 64 staged in smem as tf32 hi/lo.
// Smem row stride 68 -> all fragment gathers conflict-free.
// ---------------------------------------------------------------------------
#define KST 68
#define GEMM_SMEM_BYTES (4 * 64 * KST * 4)   // xhi,xlo,bhi,blo = 69632 B

__global__ __launch_bounds__(128) void gemm_kernel(const float* __restrict__ x,
                                                   const float* __restrict__ Bm) {
    extern __shared__ __align__(16) float sm[];
    float* xhi = sm;                  // [t 0..63][j 0..63] stride 68
    float* xlo = sm + 64 * KST;
    float* bhi = sm + 2 * 64 * KST;   // [h 0..63][j 0..63] stride 68
    float* blo = sm + 3 * 64 * KST;

    const int tid  = threadIdx.x;
    const int lane = tid & 31;
    const int wid  = tid >> 5;
    const int wt   = wid >> 1;        // 0..1 -> t offset 32*wt
    const int wh   = wid & 1;         // 0..1 -> h offset 32*wh
    const int b    = blockIdx.x >> 4;
    const int t0   = (blockIdx.x & 15) * 64;

    const int lr = lane >> 2;         // 0..7
    const int lc = lane & 3;          // 0..3

    float acc[2][4][4];
#pragma unroll
    for (int m = 0; m < 2; ++m)
#pragma unroll
        for (int n = 0; n < 4; ++n)
#pragma unroll
            for (int q = 0; q < 4; ++q) acc[m][n][q] = 0.f;

    const float4* x4 = reinterpret_cast<const float4*>(x);
    const float4* B4 = reinterpret_cast<const float4*>(Bm);

    for (int kc = 0; kc < 2; ++kc) {
        if (kc) __syncthreads();
        // Stage x chunk: 64 t x 16 float4, split hi/lo
#pragma unroll
        for (int i = 0; i < 8; ++i) {
            int f  = tid + 128 * i;
            int t  = f >> 4;
            int jq = f & 15;
            float4 v = x4[(b * TT + t0 + t) * 32 + kc * 16 + jq];
            float4 hv, lv;
            hv.x = __uint_as_float(tf32bits(v.x)); lv.x = v.x - hv.x;
            hv.y = __uint_as_float(tf32bits(v.y)); lv.y = v.y - hv.y;
            hv.z = __uint_as_float(tf32bits(v.z)); lv.z = v.z - hv.z;
            hv.w = __uint_as_float(tf32bits(v.w)); lv.w = v.w - hv.w;
            *reinterpret_cast<float4*>(&xhi[t * KST + jq * 4]) = hv;
            *reinterpret_cast<float4*>(&xlo[t * KST + jq * 4]) = lv;
        }
        // Stage B chunk: 64 h x 16 float4, split hi/lo
#pragma unroll
        for (int i = 0; i < 8; ++i) {
            int f  = tid + 128 * i;
            int h  = f >> 4;
            int jq = f & 15;
            float4 v = B4[h * 32 + kc * 16 + jq];
            float4 hv, lv;
            hv.x = __uint_as_float(tf32bits(v.x)); lv.x = v.x - hv.x;
            hv.y = __uint_as_float(tf32bits(v.y)); lv.y = v.y - hv.y;
            hv.z = __uint_as_float(tf32bits(v.z)); lv.z = v.z - hv.z;
            hv.w = __uint_as_float(tf32bits(v.w)); lv.w = v.w - hv.w;
            *reinterpret_cast<float4*>(&bhi[h * KST + jq * 4]) = hv;
            *reinterpret_cast<float4*>(&blo[h * KST + jq * 4]) = lv;
        }
        __syncthreads();

#pragma unroll
        for (int ks = 0; ks < 8; ++ks) {
            const int j0 = ks * 8;
            // A fragments (hi & lo) for 2 m-tiles
            unsigned ah[2][4], al[2][4];
#pragma unroll
            for (int m = 0; m < 2; ++m) {
                int base = (wt * 32 + m * 16 + lr) * KST + j0 + lc;
                ah[m][0] = fbits(xhi[base]);
                ah[m][1] = fbits(xhi[base + 8 * KST]);
                ah[m][2] = fbits(xhi[base + 4]);
                ah[m][3] = fbits(xhi[base + 8 * KST + 4]);
                al[m][0] = fbits(xlo[base]);
                al[m][1] = fbits(xlo[base + 8 * KST]);
                al[m][2] = fbits(xlo[base + 4]);
                al[m][3] = fbits(xlo[base + 8 * KST + 4]);
            }
#pragma unroll
            for (int n = 0; n < 4; ++n) {
                int hb = (wh * 32 + n * 8 + lr) * KST + j0 + lc;
                unsigned bh0 = fbits(bhi[hb]);
                unsigned bh1 = fbits(bhi[hb + 4]);
                unsigned bl0 = fbits(blo[hb]);
                unsigned bl1 = fbits(blo[hb + 4]);
#pragma unroll
                for (int m = 0; m < 2; ++m) {
                    mma_tf32(acc[m][n][0], acc[m][n][1], acc[m][n][2], acc[m][n][3],
                             ah[m][0], ah[m][1], ah[m][2], ah[m][3], bh0, bh1);
                    mma_tf32(acc[m][n][0], acc[m][n][1], acc[m][n][2], acc[m][n][3],
                             ah[m][0], ah[m][1], ah[m][2], ah[m][3], bl0, bl1);
                    mma_tf32(acc[m][n][0], acc[m][n][1], acc[m][n][2], acc[m][n][3],
                             al[m][0], al[m][1], al[m][2], al[m][3], bh0, bh1);
                }
            }
        }
    }
    __syncthreads();

    // Epilogue: stage D into smem as [h][t] (stride 68), then coalesced
    // float4 writes of g_Bxt[b][h][t] rows.
    float* sD = sm;   // 64 * 68 floats, aliases xhi (safe after sync)
#pragma unroll
    for (int m = 0; m < 2; ++m)
#pragma unroll
        for (int n = 0; n < 4; ++n) {
            int tr = wt * 32 + m * 16 + lr;
            int hc = wh * 32 + n * 8 + 2 * lc;
            sD[hc * KST + tr]            = acc[m][n][0];
            sD[(hc + 1) * KST + tr]      = acc[m][n][1];
            sD[hc * KST + tr + 8]        = acc[m][n][2];
            sD[(hc + 1) * KST + tr + 8]  = acc[m][n][3];
        }
    __syncthreads();
    {
        int h  = tid >> 1;
        int tq = tid & 1;
        float* dst = &g_Bxt[(b * HH + h) * TT + t0 + tq * 32];
        const float* srcp = &sD[h * KST + tq * 32];
#pragma unroll
        for (int i = 0; i < 8; ++i) {
            *reinterpret_cast<float4*>(dst + i * 4) =
                *reinterpret_cast<const float4*>(srcp + i * 4);
        }
    }
}

// ---------------------------------------------------------------------------
// Kernel 2: complex linear scan  y_t = lam*y_{t-1} + Bx_t,  y_{-1} = 1.
// (Round-2 version, verbatim: best measured config.)
// ---------------------------------------------------------------------------
__global__ __launch_bounds__(512) void scan_kernel(const float* __restrict__ nu,
                                                   const float* __restrict__ theta,
                                                   float* __restrict__ out) {
    __shared__ float svr[64 * 9];
    __shared__ float svi[64 * 9];
    __shared__ float sbr[8], sbi[8];

    const int tid = threadIdx.x;
    const int tg  = tid >> 3;          // 0..63  t-chunk
    const int hl  = tid & 7;           // 0..7
    const int b   = blockIdx.y;
    const int hb  = blockIdx.x * 8;
    const int h   = hb + hl;

    const float mag = expf(-expf(nu[h]));
    const float lr  = mag * cosf(theta[h]);
    const float li  = mag * sinf(theta[h]);

    float u[16];
    const float4* src =
        reinterpret_cast<const float4*>(&g_Bxt[(b * HH + h) * TT + tg * 16]);
#pragma unroll
    for (int q = 0; q < 4; ++q) {
        float4 v = src[q];
        u[4 * q + 0] = v.x; u[4 * q + 1] = v.y;
        u[4 * q + 2] = v.z; u[4 * q + 3] = v.w;
    }

    float yr = 0.f, yi = 0.f;
#pragma unroll
    for (int k = 0; k < 16; ++k) {
        float nyr = fmaf(lr, yr, fmaf(-li, yi, u[k]));
        float nyi = fmaf(lr, yi, li * yr);
        yr = nyr; yi = nyi;
    }
    svr[tg * 9 + hl] = yr;
    svi[tg * 9 + hl] = yi;
    __syncthreads();

    const int lane = tid & 31;
    const int wid  = tid >> 5;          // 0..15
    const int hw   = wid & 7;
    const int half = wid >> 3;
    const int c    = half * 32 + lane;

    const int   h2   = hb + hw;
    const float mag2 = expf(-expf(nu[h2]));
    float ar = mag2 * cosf(theta[h2]);
    float ai = mag2 * sinf(theta[h2]);

    float pr = ar, pi = ai;
#pragma unroll
    for (int s = 0; s < 4; ++s) {
        float nr = pr * pr - pi * pi;
        float ni = 2.f * pr * pi;
        pr = nr; pi = ni;
    }
    float Pr[5], Pi[5];
    Pr[0] = pr; Pi[0] = pi;
#pragma unroll
    for (int d = 1; d < 5; ++d) {
        Pr[d] = Pr[d - 1] * Pr[d - 1] - Pi[d - 1] * Pi[d - 1];
        Pi[d] = 2.f * Pr[d - 1] * Pi[d - 1];
    }
    const float P32r = Pr[4] * Pr[4] - Pi[4] * Pi[4];
    const float P32i = 2.f * Pr[4] * Pi[4];

    float Vr = svr[c * 9 + hw];
    float Vi = svi[c * 9 + hw];
#pragma unroll
    for (int d = 0; d < 5; ++d) {
        int sh = 1 << d;
        float orr = __shfl_up_sync(0xffffffffu, Vr, sh);
        float oii = __shfl_up_sync(0xffffffffu, Vi, sh);
        if (lane >= sh) {
            float nVr = Vr + (Pr[d] * orr - Pi[d] * oii);
            float nVi = Vi + (Pr[d] * oii + Pi[d] * orr);
            Vr = nVr; Vi = nVi;
        }
    }
    if (half == 0 && lane == 31) { sbr[hw] = Vr; sbi[hw] = Vi; }
    __syncthreads();

    float Br_ = 1.f, Bi_ = 0.f;
    if (half) {
        Br_ = P32r + sbr[hw];
        Bi_ = P32i + sbi[hw];
    }
    float Wr = __shfl_up_sync(0xffffffffu, Vr, 1);
    float Wi = __shfl_up_sync(0xffffffffu, Vi, 1);
    if (lane == 0) { Wr = 0.f; Wi = 0.f; }
    float qr = 1.f, qi = 0.f;
#pragma unroll
    for (int d = 0; d < 5; ++d) {
        if ((lane >> d) & 1) {
            float nr = qr * Pr[d] - qi * Pi[d];
            float ni = qr * Pi[d] + qi * Pr[d];
            qr = nr; qi = ni;
        }
    }
    svr[c * 9 + hw] = Wr + (qr * Br_ - qi * Bi_);
    svi[c * 9 + hw] = Wi + (qr * Bi_ + qi * Br_);
    __syncthreads();

    yr = svr[tg * 9 + hl];
    yi = svi[tg * 9 + hl];
    float* op = out + (b * TT + tg * 16) * (2 * HH) + h;
#pragma unroll
    for (int k = 0; k < 16; ++k) {
        float nyr = fmaf(lr, yr, fmaf(-li, yi, u[k]));
        float nyi = fmaf(lr, yi, li * yr);
        yr = nyr; yi = nyi;
        op[k * 128]      = yr;
        op[k * 128 + 64] = yi;
    }
}

// ---------------------------------------------------------------------------
extern "C" void kernel_launch(void* const* d_in, const int* in_sizes, int n_in,
                              void* d_out, int out_size) {
    const float* x     = (const float*)d_in[0];   // [16,1024,128]
    const float* Bm    = (const float*)d_in[1];   // [64,128]
    const float* nu    = (const float*)d_in[2];   // [64]
    const float* theta = (const float*)d_in[3];   // [64]
    float* out = (float*)d_out;                   // [16,1024,128]

    cudaFuncSetAttribute(gemm_kernel,
                         cudaFuncAttributeMaxDynamicSharedMemorySize,
                         GEMM_SMEM_BYTES);
    gemm_kernel<<<256, 128, GEMM_SMEM_BYTES>>>(x, Bm);
    scan_kernel<<<dim3(8, 16), 512>>>(nu, theta, out);
}